// round 1
// baseline (speedup 1.0000x reference)
#include <cuda_runtime.h>

#define NN 100000
#define DD 64
#define NE 1200000

// scratch: x1 = A1 @ all_emb  (25.6 MB, __device__ global per allocation rules)
__device__ float g_x1[NN * DD];

__global__ void zero_kernel(float* __restrict__ p, int n4) {
    int i = blockIdx.x * blockDim.x + threadIdx.x;
    if (i < n4) ((float4*)p)[i] = make_float4(0.f, 0.f, 0.f, 0.f);
}

// One edge handled by 16 threads; each thread moves 4 consecutive floats.
// Gather x[col] (float4), scatter atomicAdd into out[row].
__global__ void spmm_kernel(const float* __restrict__ x,
                            const float* __restrict__ vals,
                            const float* __restrict__ du,
                            const int*   __restrict__ rows,
                            const int*   __restrict__ cols,
                            float*       __restrict__ out,
                            float scale) {
    unsigned gid = blockIdx.x * blockDim.x + threadIdx.x;
    unsigned e   = gid >> 4;
    if (e >= NE) return;
    unsigned lane = gid & 15u;

    float u = du[e];
    // keep iff (u + 0.7) >= 1.0 in f32, matching reference exactly
    if (u + 0.7f < 1.0f) return;
    float v = (vals[e] / 0.7f) * scale;

    int c = cols[e];
    int r = rows[e];
    float4 m = ((const float4*)(x + (size_t)c * DD))[lane];
    float* dst = out + (size_t)r * DD + lane * 4;
    atomicAdd(dst + 0, v * m.x);
    atomicAdd(dst + 1, v * m.y);
    atomicAdd(dst + 2, v * m.z);
    atomicAdd(dst + 3, v * m.w);
}

// out[i][j] = (dot(emb[i], W[j]) + b[j] + x1[i][j]) / 3
// 256 threads/block -> 4 nodes/block. W staged in padded shared (no bank conflicts).
__global__ void fc_kernel(const float* __restrict__ emb,
                          const float* __restrict__ W,
                          const float* __restrict__ b,
                          const float* __restrict__ x1,
                          float*       __restrict__ out) {
    __shared__ float Ws[DD][DD + 1];
    __shared__ float bs[DD];
    __shared__ float es[4][DD];

    int tid = threadIdx.x;           // 0..255
    int nl  = tid >> 6;              // node-local 0..3
    int col = tid & 63;              // output column

    #pragma unroll
    for (int i = tid; i < DD * DD; i += 256)
        Ws[i >> 6][i & 63] = W[i];
    if (tid < DD) bs[tid] = b[tid];

    int node = blockIdx.x * 4 + nl;  // NN % 4 == 0, no tail
    es[nl][col] = emb[(size_t)node * DD + col];
    __syncthreads();

    float acc = bs[col];
    #pragma unroll
    for (int k = 0; k < DD; k++)
        acc = fmaf(es[nl][k], Ws[col][k], acc);

    size_t idx = (size_t)node * DD + col;
    out[idx] = (acc + x1[idx]) * (1.0f / 3.0f);
}

extern "C" void kernel_launch(void* const* d_in, const int* in_sizes, int n_in,
                              void* d_out, int out_size) {
    const float* emb  = (const float*)d_in[0];
    const float* W    = (const float*)d_in[1];
    const float* b    = (const float*)d_in[2];
    const float* vals = (const float*)d_in[3];
    const float* du   = (const float*)d_in[4];   // [2, E]
    const int*   rows = (const int*)d_in[5];
    const int*   cols = (const int*)d_in[6];
    float* out = (float*)d_out;

    float* x1 = nullptr;
    cudaGetSymbolAddress((void**)&x1, g_x1);

    // 1) x1 = 0
    int n4 = NN * DD / 4;
    zero_kernel<<<(n4 + 255) / 256, 256>>>(x1, n4);

    // 2) x1 += A1 @ emb   (layer-0 dropout)
    int sblocks = (NE * 16 + 255) / 256;
    spmm_kernel<<<sblocks, 256>>>(emb, vals, du, rows, cols, x1, 1.0f);

    // 3) out = (fc(emb) + x1) / 3
    fc_kernel<<<NN / 4, 256>>>(emb, W, b, x1, out);

    // 4) out += (A2 @ x1) / 3   (layer-1 dropout, /3 folded into edge weight)
    spmm_kernel<<<sblocks, 256>>>(x1, vals, du + NE, rows, cols, out,
                                  1.0f / 3.0f);
}

// round 3
// speedup vs baseline: 1.6490x; 1.6490x over previous
#include <cuda_runtime.h>

#define NN 100000
#define DD 64
#define NE 1200000

// scratch: x1 = A1 @ all_emb  (25.6 MB, __device__ global per allocation rules)
__device__ float g_x1[NN * DD];

__device__ __forceinline__ void red_add_v4(float* addr, float a, float b,
                                           float c, float d) {
    asm volatile("red.global.add.v4.f32 [%0], {%1, %2, %3, %4};"
                 :: "l"(addr), "f"(a), "f"(b), "f"(c), "f"(d)
                 : "memory");
}

__global__ void zero_kernel(float* __restrict__ p, int n4) {
    int i = blockIdx.x * blockDim.x + threadIdx.x;
    if (i < n4) ((float4*)p)[i] = make_float4(0.f, 0.f, 0.f, 0.f);
}

// One edge handled by 8 threads; each thread moves 2 float4s (32B).
// Gather x[col] coalesced, scatter via red.global.add.v4.f32 into out[row].
__global__ void spmm_kernel(const float* __restrict__ x,
                            const float* __restrict__ vals,
                            const float* __restrict__ du,
                            const int*   __restrict__ rows,
                            const int*   __restrict__ cols,
                            float*       __restrict__ out,
                            float scale) {
    unsigned gid = blockIdx.x * blockDim.x + threadIdx.x;
    unsigned e   = gid >> 3;
    if (e >= NE) return;
    unsigned lane = gid & 7u;

    float u = du[e];
    // keep iff (u + 0.7) >= 1.0 in f32, matching reference exactly
    if (u + 0.7f < 1.0f) return;
    float v = (vals[e] / 0.7f) * scale;

    int c = cols[e];
    int r = rows[e];
    const float4* src = (const float4*)(x + (size_t)c * DD);
    float4 m0 = src[lane];
    float4 m1 = src[lane + 8];
    float* dst = out + (size_t)r * DD;
    red_add_v4(dst + lane * 4,       v * m0.x, v * m0.y, v * m0.z, v * m0.w);
    red_add_v4(dst + (lane + 8) * 4, v * m1.x, v * m1.y, v * m1.z, v * m1.w);
}

// out[i][j] = (dot(emb[i], W[j]) + b[j] + x1[i][j]) / 3
// 256 threads/block -> 4 nodes/block. W staged in padded shared (no bank conflicts).
__global__ void fc_kernel(const float* __restrict__ emb,
                          const float* __restrict__ W,
                          const float* __restrict__ b,
                          const float* __restrict__ x1,
                          float*       __restrict__ out) {
    __shared__ float Ws[DD][DD + 1];
    __shared__ float bs[DD];
    __shared__ float es[4][DD];

    int tid = threadIdx.x;           // 0..255
    int nl  = tid >> 6;              // node-local 0..3
    int col = tid & 63;              // output column

    #pragma unroll
    for (int i = tid; i < DD * DD; i += 256)
        Ws[i >> 6][i & 63] = W[i];
    if (tid < DD) bs[tid] = b[tid];

    int node = blockIdx.x * 4 + nl;  // NN % 4 == 0, no tail
    es[nl][col] = emb[(size_t)node * DD + col];
    __syncthreads();

    float acc = bs[col];
    #pragma unroll
    for (int k = 0; k < DD; k++)
        acc = fmaf(es[nl][k], Ws[col][k], acc);

    size_t idx = (size_t)node * DD + col;
    out[idx] = (acc + x1[idx]) * (1.0f / 3.0f);
}

extern "C" void kernel_launch(void* const* d_in, const int* in_sizes, int n_in,
                              void* d_out, int out_size) {
    const float* emb  = (const float*)d_in[0];
    const float* W    = (const float*)d_in[1];
    const float* b    = (const float*)d_in[2];
    const float* vals = (const float*)d_in[3];
    const float* du   = (const float*)d_in[4];   // [2, E]
    const int*   rows = (const int*)d_in[5];
    const int*   cols = (const int*)d_in[6];
    float* out = (float*)d_out;

    float* x1 = nullptr;
    cudaGetSymbolAddress((void**)&x1, g_x1);

    // 1) x1 = 0
    int n4 = NN * DD / 4;
    zero_kernel<<<(n4 + 255) / 256, 256>>>(x1, n4);

    // 2) x1 += A1 @ emb   (layer-0 dropout)
    int sblocks = (NE * 8 + 255) / 256;
    spmm_kernel<<<sblocks, 256>>>(emb, vals, du, rows, cols, x1, 1.0f);

    // 3) out = (fc(emb) + x1) / 3
    fc_kernel<<<NN / 4, 256>>>(emb, W, b, x1, out);

    // 4) out += (A2 @ x1) / 3   (layer-1 dropout, /3 folded into edge weight)
    spmm_kernel<<<sblocks, 256>>>(x1, vals, du + NE, rows, cols, out,
                                  1.0f / 3.0f);
}

// round 4
// speedup vs baseline: 1.9626x; 1.1902x over previous
#include <cuda_runtime.h>

#define NN 100000
#define DD 64
#define NE 1200000
#define NEH (NE / 2)

// scratch: x1 = A1 @ all_emb  (25.6 MB, __device__ global per allocation rules)
__device__ float g_x1[NN * DD];

__device__ __forceinline__ void red_add_v4(float* addr, float a, float b,
                                           float c, float d) {
    asm volatile("red.global.add.v4.f32 [%0], {%1, %2, %3, %4};"
                 :: "l"(addr), "f"(a), "f"(b), "f"(c), "f"(d)
                 : "memory");
}

__global__ void zero_kernel(float* __restrict__ p, int n4) {
    int i = blockIdx.x * blockDim.x + threadIdx.x;
    if (i < n4) ((float4*)p)[i] = make_float4(0.f, 0.f, 0.f, 0.f);
}

// Each thread handles TWO edges (e, e+NE/2) with 8 lanes per edge, 2 float4
// per lane. Metadata for both edges is loaded unconditionally & in parallel
// (streaming arrays -> no extra traffic), so the dependent chain is just
// metadata -> gather -> red, with 2-way MLP across edges.
__global__ void spmm_kernel(const float* __restrict__ x,
                            const float* __restrict__ vals,
                            const float* __restrict__ du,
                            const int*   __restrict__ rows,
                            const int*   __restrict__ cols,
                            float*       __restrict__ out,
                            float scale) {
    unsigned gid = blockIdx.x * blockDim.x + threadIdx.x;
    unsigned e0  = gid >> 3;
    if (e0 >= NEH) return;
    unsigned e1   = e0 + NEH;
    unsigned lane = gid & 7u;

    // parallel metadata loads for both edges
    float u0 = du[e0],  u1 = du[e1];
    float w0 = vals[e0], w1 = vals[e1];
    int   c0 = cols[e0], c1 = cols[e1];
    int   r0 = rows[e0], r1 = rows[e1];

    bool k0 = (u0 + 0.7f) >= 1.0f;   // keep predicate, matches reference f32
    bool k1 = (u1 + 0.7f) >= 1.0f;
    float v0 = (w0 / 0.7f) * scale;
    float v1 = (w1 / 0.7f) * scale;

    float4 a0, a1, b0, b1;
    const float4* s0 = (const float4*)(x + (size_t)c0 * DD);
    const float4* s1 = (const float4*)(x + (size_t)c1 * DD);
    if (k0) { a0 = s0[lane]; a1 = s0[lane + 8]; }
    if (k1) { b0 = s1[lane]; b1 = s1[lane + 8]; }

    if (k0) {
        float* d0 = out + (size_t)r0 * DD;
        red_add_v4(d0 + lane * 4,       v0 * a0.x, v0 * a0.y, v0 * a0.z, v0 * a0.w);
        red_add_v4(d0 + (lane + 8) * 4, v0 * a1.x, v0 * a1.y, v0 * a1.z, v0 * a1.w);
    }
    if (k1) {
        float* d1 = out + (size_t)r1 * DD;
        red_add_v4(d1 + lane * 4,       v1 * b0.x, v1 * b0.y, v1 * b0.z, v1 * b0.w);
        red_add_v4(d1 + (lane + 8) * 4, v1 * b1.x, v1 * b1.y, v1 * b1.z, v1 * b1.w);
    }
}

// out[i][j] = (dot(emb[i], W[j]) + b[j] + x1[i][j]) / 3
// 256 threads/block -> 4 nodes/block. W staged in padded shared (no bank conflicts).
__global__ void fc_kernel(const float* __restrict__ emb,
                          const float* __restrict__ W,
                          const float* __restrict__ b,
                          const float* __restrict__ x1,
                          float*       __restrict__ out) {
    __shared__ float Ws[DD][DD + 1];
    __shared__ float bs[DD];
    __shared__ float es[4][DD];

    int tid = threadIdx.x;           // 0..255
    int nl  = tid >> 6;              // node-local 0..3
    int col = tid & 63;              // output column

    #pragma unroll
    for (int i = tid; i < DD * DD; i += 256)
        Ws[i >> 6][i & 63] = W[i];
    if (tid < DD) bs[tid] = b[tid];

    int node = blockIdx.x * 4 + nl;  // NN % 4 == 0, no tail
    es[nl][col] = emb[(size_t)node * DD + col];
    __syncthreads();

    float acc = bs[col];
    #pragma unroll
    for (int k = 0; k < DD; k++)
        acc = fmaf(es[nl][k], Ws[col][k], acc);

    size_t idx = (size_t)node * DD + col;
    out[idx] = (acc + x1[idx]) * (1.0f / 3.0f);
}

extern "C" void kernel_launch(void* const* d_in, const int* in_sizes, int n_in,
                              void* d_out, int out_size) {
    const float* emb  = (const float*)d_in[0];
    const float* W    = (const float*)d_in[1];
    const float* b    = (const float*)d_in[2];
    const float* vals = (const float*)d_in[3];
    const float* du   = (const float*)d_in[4];   // [2, E]
    const int*   rows = (const int*)d_in[5];
    const int*   cols = (const int*)d_in[6];
    float* out = (float*)d_out;

    float* x1 = nullptr;
    cudaGetSymbolAddress((void**)&x1, g_x1);

    // 1) x1 = 0
    int n4 = NN * DD / 4;
    zero_kernel<<<(n4 + 255) / 256, 256>>>(x1, n4);

    // 2) x1 += A1 @ emb   (layer-0 dropout)
    int sblocks = (NEH * 8 + 255) / 256;
    spmm_kernel<<<sblocks, 256>>>(emb, vals, du, rows, cols, x1, 1.0f);

    // 3) out = (fc(emb) + x1) / 3
    fc_kernel<<<NN / 4, 256>>>(emb, W, b, x1, out);

    // 4) out += (A2 @ x1) / 3   (layer-1 dropout, /3 folded into edge weight)
    spmm_kernel<<<sblocks, 256>>>(x1, vals, du + NE, rows, cols, out,
                                  1.0f / 3.0f);
}

// round 5
// speedup vs baseline: 2.1020x; 1.0710x over previous
#include <cuda_runtime.h>

#define NN 100000
#define DD 64
#define NE 1200000
#define NEQ (NE / 4)

// scratch: x1 = A1 @ all_emb  (25.6 MB, __device__ global per allocation rules)
__device__ float g_x1[NN * DD];

__device__ __forceinline__ void red_add_v4(float* addr, float a, float b,
                                           float c, float d) {
    asm volatile("red.global.add.v4.f32 [%0], {%1, %2, %3, %4};"
                 :: "l"(addr), "f"(a), "f"(b), "f"(c), "f"(d)
                 : "memory");
}

__global__ void zero_kernel(float* __restrict__ p, int n4) {
    int i = blockIdx.x * blockDim.x + threadIdx.x;
    if (i < n4) ((float4*)p)[i] = make_float4(0.f, 0.f, 0.f, 0.f);
}

// Each thread handles FOUR edges (e, e+E/4, e+E/2, e+3E/4) with 8 lanes per
// edge, 2 float4 per lane. All metadata loaded unconditionally & in parallel
// (streaming arrays, zero extra traffic), all 8 gather float4s in flight
// together -> 4-way MLP on the gather-miss chain.
__global__ void spmm_kernel(const float* __restrict__ x,
                            const float* __restrict__ vals,
                            const float* __restrict__ du,
                            const int*   __restrict__ rows,
                            const int*   __restrict__ cols,
                            float*       __restrict__ out,
                            float scale) {
    unsigned gid = blockIdx.x * blockDim.x + threadIdx.x;
    unsigned e   = gid >> 3;
    if (e >= NEQ) return;
    unsigned lane = gid & 7u;

    unsigned ei[4] = {e, e + NEQ, e + 2 * NEQ, e + 3 * NEQ};

    float u[4], w[4];
    int   c[4], r[4];
    #pragma unroll
    for (int i = 0; i < 4; i++) {
        u[i] = du[ei[i]];
        w[i] = vals[ei[i]];
        c[i] = cols[ei[i]];
        r[i] = rows[ei[i]];
    }

    bool  k[4];
    float v[4];
    #pragma unroll
    for (int i = 0; i < 4; i++) {
        k[i] = (u[i] + 0.7f) >= 1.0f;   // keep predicate, matches ref f32
        v[i] = (w[i] / 0.7f) * scale;
    }

    float4 m0[4], m1[4];
    #pragma unroll
    for (int i = 0; i < 4; i++) {
        const float4* s = (const float4*)(x + (size_t)c[i] * DD);
        if (k[i]) { m0[i] = s[lane]; m1[i] = s[lane + 8]; }
    }

    #pragma unroll
    for (int i = 0; i < 4; i++) {
        if (k[i]) {
            float* d = out + (size_t)r[i] * DD;
            float vi = v[i];
            red_add_v4(d + lane * 4,
                       vi * m0[i].x, vi * m0[i].y, vi * m0[i].z, vi * m0[i].w);
            red_add_v4(d + (lane + 8) * 4,
                       vi * m1[i].x, vi * m1[i].y, vi * m1[i].z, vi * m1[i].w);
        }
    }
}

// out[i][j] = (dot(emb[i], W[j]) + b[j] + x1[i][j]) / 3
// Grid-stride persistent blocks: W/b staged into shared ONCE per block,
// then the block loops over groups of 4 nodes. Kills the 400 MB of W reloads.
__global__ void fc_kernel(const float* __restrict__ emb,
                          const float* __restrict__ W,
                          const float* __restrict__ b,
                          const float* __restrict__ x1,
                          float*       __restrict__ out,
                          int ngroups) {
    __shared__ float Ws[DD][DD + 1];
    __shared__ float bs[DD];

    int tid = threadIdx.x;           // 0..255
    int nl  = tid >> 6;              // node-local 0..3
    int col = tid & 63;              // output column

    #pragma unroll
    for (int i = tid; i < DD * DD; i += 256)
        Ws[i >> 6][i & 63] = W[i];
    if (tid < DD) bs[tid] = b[tid];
    __syncthreads();

    for (int g = blockIdx.x; g < ngroups; g += gridDim.x) {
        int node = g * 4 + nl;       // NN % 4 == 0, no tail
        size_t base = (size_t)node * DD;

        // load this node's embedding row into registers via float4
        float4 e0 = ((const float4*)(emb + base))[(col & 15)];
        // each thread needs the whole row; use shared staging instead:
        __shared__ float es[4][DD];
        es[nl][col] = emb[base + col];
        (void)e0;
        __syncthreads();

        float acc = bs[col];
        #pragma unroll
        for (int kk = 0; kk < DD; kk++)
            acc = fmaf(es[nl][kk], Ws[col][kk], acc);

        out[base + col] = (acc + x1[base + col]) * (1.0f / 3.0f);
        __syncthreads();
    }
}

extern "C" void kernel_launch(void* const* d_in, const int* in_sizes, int n_in,
                              void* d_out, int out_size) {
    const float* emb  = (const float*)d_in[0];
    const float* W    = (const float*)d_in[1];
    const float* b    = (const float*)d_in[2];
    const float* vals = (const float*)d_in[3];
    const float* du   = (const float*)d_in[4];   // [2, E]
    const int*   rows = (const int*)d_in[5];
    const int*   cols = (const int*)d_in[6];
    float* out = (float*)d_out;

    float* x1 = nullptr;
    cudaGetSymbolAddress((void**)&x1, g_x1);

    // 1) x1 = 0
    int n4 = NN * DD / 4;
    zero_kernel<<<(n4 + 255) / 256, 256>>>(x1, n4);

    // 2) x1 += A1 @ emb   (layer-0 dropout)
    int sblocks = (NEQ * 8 + 255) / 256;
    spmm_kernel<<<sblocks, 256>>>(emb, vals, du, rows, cols, x1, 1.0f);

    // 3) out = (fc(emb) + x1) / 3   (persistent blocks, W loaded once each)
    fc_kernel<<<1184, 256>>>(emb, W, b, x1, out, NN / 4);

    // 4) out += (A2 @ x1) / 3   (layer-1 dropout, /3 folded into edge weight)
    spmm_kernel<<<sblocks, 256>>>(x1, vals, du + NE, rows, cols, out,
                                  1.0f / 3.0f);
}

// round 6
// speedup vs baseline: 2.8530x; 1.3573x over previous
#include <cuda_runtime.h>

#define NN 100000
#define DD 64
#define NE 1200000
#define NEH (NE / 2)

// scratch: x1 = A1 @ all_emb  (25.6 MB, __device__ global per allocation rules)
__device__ float g_x1[NN * DD];

// ---------------- packed f32x2 helpers (Blackwell FFMA2 path) ----------------
__device__ __forceinline__ unsigned long long pk2(float lo, float hi) {
    unsigned long long r;
    asm("mov.b64 %0, {%1, %2};" : "=l"(r) : "f"(lo), "f"(hi));
    return r;
}
__device__ __forceinline__ void upk2(float& lo, float& hi, unsigned long long v) {
    asm("mov.b64 {%0, %1}, %2;" : "=f"(lo), "=f"(hi) : "l"(v));
}
__device__ __forceinline__ void ffma2(unsigned long long& d,
                                      unsigned long long a,
                                      unsigned long long b) {
    asm("fma.rn.f32x2 %0, %1, %2, %0;" : "+l"(d) : "l"(a), "l"(b));
}

__device__ __forceinline__ void red_add_v4(float* addr, float a, float b,
                                           float c, float d) {
    asm volatile("red.global.add.v4.f32 [%0], {%1, %2, %3, %4};"
                 :: "l"(addr), "f"(a), "f"(b), "f"(c), "f"(d)
                 : "memory");
}

__global__ void zero_kernel(float* __restrict__ p, int n4) {
    int i = blockIdx.x * blockDim.x + threadIdx.x;
    if (i < n4) ((float4*)p)[i] = make_float4(0.f, 0.f, 0.f, 0.f);
}

// Each thread handles TWO edges (e, e+NE/2) with 8 lanes per edge, 2 float4
// per lane. Metadata loaded unconditionally & in parallel; chain is
// metadata -> gather -> red with 2-way MLP. (ILP=2 proven best: 30 regs.)
__global__ void spmm_kernel(const float* __restrict__ x,
                            const float* __restrict__ vals,
                            const float* __restrict__ du,
                            const int*   __restrict__ rows,
                            const int*   __restrict__ cols,
                            float*       __restrict__ out,
                            float scale) {
    unsigned gid = blockIdx.x * blockDim.x + threadIdx.x;
    unsigned e0  = gid >> 3;
    if (e0 >= NEH) return;
    unsigned e1   = e0 + NEH;
    unsigned lane = gid & 7u;

    float u0 = du[e0],  u1 = du[e1];
    float w0 = vals[e0], w1 = vals[e1];
    int   c0 = cols[e0], c1 = cols[e1];
    int   r0 = rows[e0], r1 = rows[e1];

    bool k0 = (u0 + 0.7f) >= 1.0f;   // keep predicate, matches reference f32
    bool k1 = (u1 + 0.7f) >= 1.0f;
    float v0 = (w0 / 0.7f) * scale;
    float v1 = (w1 / 0.7f) * scale;

    float4 a0, a1, b0, b1;
    const float4* s0 = (const float4*)(x + (size_t)c0 * DD);
    const float4* s1 = (const float4*)(x + (size_t)c1 * DD);
    if (k0) { a0 = s0[lane]; a1 = s0[lane + 8]; }
    if (k1) { b0 = s1[lane]; b1 = s1[lane + 8]; }

    if (k0) {
        float* d0 = out + (size_t)r0 * DD;
        red_add_v4(d0 + lane * 4,       v0 * a0.x, v0 * a0.y, v0 * a0.z, v0 * a0.w);
        red_add_v4(d0 + (lane + 8) * 4, v0 * a1.x, v0 * a1.y, v0 * a1.z, v0 * a1.w);
    }
    if (k1) {
        float* d1 = out + (size_t)r1 * DD;
        red_add_v4(d1 + lane * 4,       v1 * b0.x, v1 * b0.y, v1 * b0.z, v1 * b0.w);
        red_add_v4(d1 + (lane + 8) * 4, v1 * b1.x, v1 * b1.y, v1 * b1.z, v1 * b1.w);
    }
}

// Register-tiled fc: out[n][c] = (dot(emb[n], W[c]) + b[c] + x1[n][c]) / 3.
// Block tile: 64 nodes x 64 cols. Thread: 4 nodes (nl, nl+16, nl+32, nl+48)
// x 4 cols (c0..c0+3), 16 accumulators packed as 8 f32x2 pairs.
// es[64][65]: a-reads broadcast (same node across 16 lanes) -> conflict-free.
// Wp[64][32] float2: W pre-paired over adjacent cols so FFMA2 needs no b-pack.
__global__ void __launch_bounds__(256)
fc_kernel(const float* __restrict__ emb,
          const float* __restrict__ W,
          const float* __restrict__ b,
          const float* __restrict__ x1,
          float*       __restrict__ out) {
    __shared__ float  es[64][65];
    __shared__ float2 Wp[64][33];   // Wp[k][j] = (W[2j][k], W[2j+1][k])

    int tid = threadIdx.x;

    // stage W paired-transposed: 2048 float2, 8 per thread
    #pragma unroll
    for (int i = tid; i < 32 * 64; i += 256) {
        int j = i >> 6;          // col pair 0..31
        int k = i & 63;          // k index
        Wp[k][j] = make_float2(W[(2 * j) * DD + k], W[(2 * j + 1) * DD + k]);
    }

    // stage emb tile (coalesced float4 reads)
    int n0 = blockIdx.x * 64;
    #pragma unroll
    for (int i = tid; i < 64 * 16; i += 256) {
        int n  = i >> 4;
        int kq = i & 15;
        float4 v = make_float4(0.f, 0.f, 0.f, 0.f);
        if (n0 + n < NN) v = ((const float4*)emb)[(size_t)(n0 + n) * 16 + kq];
        es[n][4 * kq + 0] = v.x;
        es[n][4 * kq + 1] = v.y;
        es[n][4 * kq + 2] = v.z;
        es[n][4 * kq + 3] = v.w;
    }
    __syncthreads();

    int nl = tid >> 4;           // node lane 0..15 (same across 16 consecutive tids)
    int cg = tid & 15;           // col group: cols 4*cg .. 4*cg+3
    int c0 = cg * 4;

    float4 bv = *(const float4*)(b + c0);
    unsigned long long bp0 = pk2(bv.x, bv.y);
    unsigned long long bp1 = pk2(bv.z, bv.w);

    unsigned long long acc[4][2];
    #pragma unroll
    for (int i = 0; i < 4; i++) { acc[i][0] = bp0; acc[i][1] = bp1; }

    #pragma unroll 8
    for (int k = 0; k < DD; k++) {
        float2 w0 = Wp[k][2 * cg];
        float2 w1 = Wp[k][2 * cg + 1];
        unsigned long long wp0 = pk2(w0.x, w0.y);
        unsigned long long wp1 = pk2(w1.x, w1.y);
        #pragma unroll
        for (int i = 0; i < 4; i++) {
            float a = es[nl + 16 * i][k];
            unsigned long long ad = pk2(a, a);
            ffma2(acc[i][0], ad, wp0);
            ffma2(acc[i][1], ad, wp1);
        }
    }

    // epilogue: fuse + x1, * 1/3. Warp covers 256B contiguous per node row.
    #pragma unroll
    for (int i = 0; i < 4; i++) {
        int n = n0 + nl + 16 * i;
        if (n < NN) {
            size_t idx = (size_t)n * 16 + cg;
            float4 xv = ((const float4*)x1)[idx];
            float l0, h0, l1, h1;
            upk2(l0, h0, acc[i][0]);
            upk2(l1, h1, acc[i][1]);
            float4 o;
            o.x = (l0 + xv.x) * (1.0f / 3.0f);
            o.y = (h0 + xv.y) * (1.0f / 3.0f);
            o.z = (l1 + xv.z) * (1.0f / 3.0f);
            o.w = (h1 + xv.w) * (1.0f / 3.0f);
            ((float4*)out)[idx] = o;
        }
    }
}

extern "C" void kernel_launch(void* const* d_in, const int* in_sizes, int n_in,
                              void* d_out, int out_size) {
    const float* emb  = (const float*)d_in[0];
    const float* W    = (const float*)d_in[1];
    const float* b    = (const float*)d_in[2];
    const float* vals = (const float*)d_in[3];
    const float* du   = (const float*)d_in[4];   // [2, E]
    const int*   rows = (const int*)d_in[5];
    const int*   cols = (const int*)d_in[6];
    float* out = (float*)d_out;

    float* x1 = nullptr;
    cudaGetSymbolAddress((void**)&x1, g_x1);

    // 1) x1 = 0
    int n4 = NN * DD / 4;
    zero_kernel<<<(n4 + 255) / 256, 256>>>(x1, n4);

    // 2) x1 += A1 @ emb   (layer-0 dropout)
    int sblocks = (NEH * 8 + 255) / 256;
    spmm_kernel<<<sblocks, 256>>>(emb, vals, du, rows, cols, x1, 1.0f);

    // 3) out = (fc(emb) + x1) / 3   (register-tiled, FFMA2)
    fc_kernel<<<(NN + 63) / 64, 256>>>(emb, W, b, x1, out);

    // 4) out += (A2 @ x1) / 3   (layer-1 dropout, /3 folded into edge weight)
    spmm_kernel<<<sblocks, 256>>>(x1, vals, du + NE, rows, cols, out,
                                  1.0f / 3.0f);
}